// round 14
// baseline (speedup 1.0000x reference)
#include <cuda_runtime.h>
#include <cuda_fp16.h>

#define NN 5000      // nodes per level
#define BB 1024      // batch
#define KK 16        // fan-in
#define NLEV 9       // level applications
#define NEG_SLOPE 0.1f

#define NGRID 1000   // level-kernel blocks: 5000/1000 = 5 node-iters exactly
#define NTHR  256    // one node per block-iter, 4 fp16 lanes per thread

// fp16 activation planes, [N, B] node-major, ping-pong: 2 x 10.24 MB.
__device__ __align__(16) __half g_act[2][NN * BB];
// u16 predecessor indices: 1.44 MB
__device__ __align__(16) unsigned short g_idx[NLEV * NN * KK];
// fp32 weights (exact copy): 2.88 MB
__device__ __align__(16) float g_w[NLEV * NN * KK];

// ---------------------------------------------------------------------------
__global__ void prep_kernel(const int* __restrict__ sidx, const float* __restrict__ w) {
    int i = blockIdx.x * 256 + threadIdx.x;
    if (i < NLEV * NN * KK) {
        g_idx[i] = (unsigned short)sidx[i];
        g_w[i]   = w[i];
    }
}

// Transpose input x [B, N] fp32 -> g_act[0] [N, B] fp16
__global__ void tin_kernel(const float* __restrict__ x) {
    __shared__ float tile[32][33];
    int n = blockIdx.x * 32 + threadIdx.x;
    int b = blockIdx.y * 32 + threadIdx.y;
    if (n < NN) tile[threadIdx.y][threadIdx.x] = x[b * NN + n];
    __syncthreads();
    int b2 = blockIdx.y * 32 + threadIdx.x;
    int n2 = blockIdx.x * 32 + threadIdx.y;
    if (n2 < NN) g_act[0][n2 * BB + b2] = __float2half_rn(tile[threadIdx.x][threadIdx.y]);
}

// ---------------------------------------------------------------------------
// one edge: gather 4 halves (LDG.64), 4 fp32 FMA. s = u16 index, wk = fp32 weight.
#define EDGE(s, wk) do {                                                    \
    uint2 v = __ldg(reinterpret_cast<const uint2*>(src + (s) * BB) + t);    \
    float2 f0 = __half22float2(*reinterpret_cast<const __half2*>(&v.x));    \
    float2 f1 = __half22float2(*reinterpret_cast<const __half2*>(&v.y));    \
    a0 = fmaf(f0.x, (wk), a0);  a1 = fmaf(f0.y, (wk), a1);                  \
    a2 = fmaf(f1.x, (wk), a2);  a3 = fmaf(f1.y, (wk), a3);                  \
} while (0)

// leaky(a) == max(a, 0.1a)  (valid for slope in (0,1)): FMUL + FMNMX
#define LEAKY(a) fmaxf((a), NEG_SLOPE * (a))

// Grid-stride level kernel: one node per block-iteration.
// 256 threads x 4 fp16 lanes = 1024 batch. 5 iters per block, exact.
__global__ __launch_bounds__(NTHR, 8) void level_kernel(int ssel, int lev,
                                                        const float* __restrict__ bias_all) {
    const __half* __restrict__ src = g_act[ssel];
    __half*       __restrict__ dst = g_act[ssel ^ 1];
    const unsigned short* __restrict__ idx = g_idx + (size_t)lev * NN * KK;
    const float*          __restrict__ wt  = g_w   + (size_t)lev * NN * KK;
    const float*          __restrict__ bias = bias_all + (size_t)lev * NN;

    const int t = threadIdx.x;     // lane group: 4 halves at byte offset t*8

    for (int n = blockIdx.x; n < NN; n += NGRID) {
        // indices: 2 warp-uniform LDG.128 (16 x u16)
        const uint4* ip = reinterpret_cast<const uint4*>(idx + n * KK);
        uint4 i0 = __ldg(ip + 0);
        uint4 i1 = __ldg(ip + 1);
        const float4* wp = reinterpret_cast<const float4*>(wt + n * KK);
        float bv = __ldg(bias + n);

        float a0 = bv, a1 = bv, a2 = bv, a3 = bv;

        {   // edges 0..3
            float4 w0 = __ldg(wp + 0);
            EDGE(i0.x & 0xFFFFu, w0.x);  EDGE(i0.x >> 16, w0.y);
            EDGE(i0.y & 0xFFFFu, w0.z);  EDGE(i0.y >> 16, w0.w);
        }
        {   // edges 4..7
            float4 w1 = __ldg(wp + 1);
            EDGE(i0.z & 0xFFFFu, w1.x);  EDGE(i0.z >> 16, w1.y);
            EDGE(i0.w & 0xFFFFu, w1.z);  EDGE(i0.w >> 16, w1.w);
        }
        {   // edges 8..11
            float4 w2 = __ldg(wp + 2);
            EDGE(i1.x & 0xFFFFu, w2.x);  EDGE(i1.x >> 16, w2.y);
            EDGE(i1.y & 0xFFFFu, w2.z);  EDGE(i1.y >> 16, w2.w);
        }
        {   // edges 12..15
            float4 w3 = __ldg(wp + 3);
            EDGE(i1.z & 0xFFFFu, w3.x);  EDGE(i1.z >> 16, w3.y);
            EDGE(i1.w & 0xFFFFu, w3.z);  EDGE(i1.w >> 16, w3.w);
        }

        a0 = LEAKY(a0); a1 = LEAKY(a1); a2 = LEAKY(a2); a3 = LEAKY(a3);

        __half2 h01 = __floats2half2_rn(a0, a1);
        __half2 h23 = __floats2half2_rn(a2, a3);
        uint2 o;
        o.x = *reinterpret_cast<unsigned int*>(&h01);
        o.y = *reinterpret_cast<unsigned int*>(&h23);
        reinterpret_cast<uint2*>(dst + n * BB)[t] = o;   // STG.64
    }
}

// Reconstruct + transpose final plane -> out [B, N] fp32
__global__ void tout_kernel(int sel, float* __restrict__ out) {
    __shared__ float tile[32][33];
    int b = blockIdx.x * 32 + threadIdx.x;
    int n = blockIdx.y * 32 + threadIdx.y;
    if (n < NN) tile[threadIdx.y][threadIdx.x] = __half2float(g_act[sel][n * BB + b]);
    __syncthreads();
    int n2 = blockIdx.y * 32 + threadIdx.x;
    int b2 = blockIdx.x * 32 + threadIdx.y;
    if (n2 < NN) out[b2 * NN + n2] = tile[threadIdx.x][threadIdx.y];
}

// ---------------------------------------------------------------------------
extern "C" void kernel_launch(void* const* d_in, const int* in_sizes, int n_in,
                              void* d_out, int out_size) {
    const float* x    = (const float*)d_in[0];   // [B, N] fp32
    const int*   sidx = (const int*)d_in[1];     // [NLEV, N, K] int32
    const float* w    = (const float*)d_in[2];   // [NLEV, N, K] fp32
    const float* bias = (const float*)d_in[3];   // [NLEV, N]    fp32
    float* out = (float*)d_out;                  // [B, N] fp32

    int tot = NLEV * NN * KK;
    prep_kernel<<<(tot + 255) / 256, 256>>>(sidx, w);

    dim3 tblk(32, 32);
    dim3 tin_grid((NN + 31) / 32, BB / 32);
    tin_kernel<<<tin_grid, tblk>>>(x);

    for (int l = 0; l < NLEV; l++) {
        level_kernel<<<NGRID, NTHR>>>(l & 1, l, bias);
    }

    dim3 tout_grid(BB / 32, (NN + 31) / 32);
    tout_kernel<<<tout_grid, tblk>>>(NLEV & 1, out);
}

// round 15
// speedup vs baseline: 1.0132x; 1.0132x over previous
#include <cuda_runtime.h>
#include <cuda_fp16.h>

#define NN 5000      // nodes per level
#define BB 1024      // batch
#define KK 16        // fan-in
#define NLEV 9       // level applications
#define NEG_SLOPE 0.1f

#define NGRID 2500   // 2 node-groups of 128 threads per block -> 5000 nodes exactly
#define NTHR  256

// fp16 activation planes, [N, B] node-major, ping-pong: 2 x 10.24 MB.
__device__ __align__(16) __half g_act[2][NN * BB];
// premultiplied byte offsets into a plane: idx * BB * 2 (= idx*2048), u32: 2.88 MB
__device__ __align__(16) unsigned int g_off[NLEV * NN * KK];
// exact fp32 weights: 2.88 MB
__device__ __align__(16) float g_w[NLEV * NN * KK];

// ---------------------------------------------------------------------------
__global__ void prep_kernel(const int* __restrict__ sidx, const float* __restrict__ w) {
    int i = blockIdx.x * 256 + threadIdx.x;
    if (i < NLEV * NN * KK) {
        g_off[i] = (unsigned int)sidx[i] * (BB * 2u);   // byte offset of pred row
        g_w[i]   = w[i];
    }
}

// Transpose input x [B, N] fp32 -> g_act[0] [N, B] fp16
__global__ void tin_kernel(const float* __restrict__ x) {
    __shared__ float tile[32][33];
    int n = blockIdx.x * 32 + threadIdx.x;
    int b = blockIdx.y * 32 + threadIdx.y;
    if (n < NN) tile[threadIdx.y][threadIdx.x] = x[b * NN + n];
    __syncthreads();
    int b2 = blockIdx.y * 32 + threadIdx.x;
    int n2 = blockIdx.x * 32 + threadIdx.y;
    if (n2 < NN) g_act[0][n2 * BB + b2] = __float2half_rn(tile[threadIdx.x][threadIdx.y]);
}

// ---------------------------------------------------------------------------
// one edge: gather 8 halves (one LDG.128 at byte offset off from this thread's
// column base), 8 fp32 FMA with exact fp32 weight.
#define EDGE(off, wk) do {                                                  \
    float4 v = __ldg(reinterpret_cast<const float4*>(base + (off)));        \
    float2 f0 = __half22float2(*reinterpret_cast<const __half2*>(&v.x));    \
    float2 f1 = __half22float2(*reinterpret_cast<const __half2*>(&v.y));    \
    float2 f2 = __half22float2(*reinterpret_cast<const __half2*>(&v.z));    \
    float2 f3 = __half22float2(*reinterpret_cast<const __half2*>(&v.w));    \
    a0 = fmaf(f0.x, (wk), a0);  a1 = fmaf(f0.y, (wk), a1);                  \
    a2 = fmaf(f1.x, (wk), a2);  a3 = fmaf(f1.y, (wk), a3);                  \
    a4 = fmaf(f2.x, (wk), a4);  a5 = fmaf(f2.y, (wk), a5);                  \
    a6 = fmaf(f3.x, (wk), a6);  a7 = fmaf(f3.y, (wk), a7);                  \
} while (0)

// leaky(a) == max(a, 0.1a): FMUL + FMNMX, no branch
#define LEAKY(a) fmaxf((a), NEG_SLOPE * (a))

// One node per 128-thread group; 128 threads x 8 fp16 lanes = 1024 batch.
__global__ __launch_bounds__(NTHR, 7) void level_kernel(int ssel, int lev,
                                                        const float* __restrict__ bias_all) {
    const __half* __restrict__ src = g_act[ssel];
    __half*       __restrict__ dst = g_act[ssel ^ 1];
    const unsigned int* __restrict__ off = g_off + (size_t)lev * NN * KK;
    const float*        __restrict__ wt  = g_w   + (size_t)lev * NN * KK;
    const float*        __restrict__ bias = bias_all + (size_t)lev * NN;

    const int t   = threadIdx.x & 127;            // lane within group
    const int sub = threadIdx.x >> 7;             // group 0/1
    const int n   = blockIdx.x * 2 + sub;         // node, always < NN

    // this thread's column base inside the source plane (byte addressing)
    const char* base = reinterpret_cast<const char*>(src) + t * 16;

    float bv = __ldg(bias + n);
    float a0 = bv, a1 = bv, a2 = bv, a3 = bv;
    float a4 = bv, a5 = bv, a6 = bv, a7 = bv;

    const uint4*  op = reinterpret_cast<const uint4*>(off + n * KK);
    const float4* wp = reinterpret_cast<const float4*>(wt + n * KK);

    {   // edges 0..3
        uint4  o0 = __ldg(op + 0);
        float4 w0 = __ldg(wp + 0);
        EDGE(o0.x, w0.x); EDGE(o0.y, w0.y); EDGE(o0.z, w0.z); EDGE(o0.w, w0.w);
    }
    {   // edges 4..7
        uint4  o1 = __ldg(op + 1);
        float4 w1 = __ldg(wp + 1);
        EDGE(o1.x, w1.x); EDGE(o1.y, w1.y); EDGE(o1.z, w1.z); EDGE(o1.w, w1.w);
    }
    {   // edges 8..11
        uint4  o2 = __ldg(op + 2);
        float4 w2 = __ldg(wp + 2);
        EDGE(o2.x, w2.x); EDGE(o2.y, w2.y); EDGE(o2.z, w2.z); EDGE(o2.w, w2.w);
    }
    {   // edges 12..15
        uint4  o3 = __ldg(op + 3);
        float4 w3 = __ldg(wp + 3);
        EDGE(o3.x, w3.x); EDGE(o3.y, w3.y); EDGE(o3.z, w3.z); EDGE(o3.w, w3.w);
    }

    a0 = LEAKY(a0); a1 = LEAKY(a1); a2 = LEAKY(a2); a3 = LEAKY(a3);
    a4 = LEAKY(a4); a5 = LEAKY(a5); a6 = LEAKY(a6); a7 = LEAKY(a7);

    __half2 h0 = __floats2half2_rn(a0, a1);
    __half2 h1 = __floats2half2_rn(a2, a3);
    __half2 h2 = __floats2half2_rn(a4, a5);
    __half2 h3 = __floats2half2_rn(a6, a7);
    float4 o;
    o.x = __uint_as_float(*reinterpret_cast<unsigned int*>(&h0));
    o.y = __uint_as_float(*reinterpret_cast<unsigned int*>(&h1));
    o.z = __uint_as_float(*reinterpret_cast<unsigned int*>(&h2));
    o.w = __uint_as_float(*reinterpret_cast<unsigned int*>(&h3));
    reinterpret_cast<float4*>(dst + n * BB)[t] = o;   // STG.128
}

// Reconstruct + transpose final plane -> out [B, N] fp32
__global__ void tout_kernel(int sel, float* __restrict__ out) {
    __shared__ float tile[32][33];
    int b = blockIdx.x * 32 + threadIdx.x;
    int n = blockIdx.y * 32 + threadIdx.y;
    if (n < NN) tile[threadIdx.y][threadIdx.x] = __half2float(g_act[sel][n * BB + b]);
    __syncthreads();
    int n2 = blockIdx.y * 32 + threadIdx.x;
    int b2 = blockIdx.x * 32 + threadIdx.y;
    if (n2 < NN) out[b2 * NN + n2] = tile[threadIdx.x][threadIdx.y];
}

// ---------------------------------------------------------------------------
extern "C" void kernel_launch(void* const* d_in, const int* in_sizes, int n_in,
                              void* d_out, int out_size) {
    const float* x    = (const float*)d_in[0];   // [B, N] fp32
    const int*   sidx = (const int*)d_in[1];     // [NLEV, N, K] int32
    const float* w    = (const float*)d_in[2];   // [NLEV, N, K] fp32
    const float* bias = (const float*)d_in[3];   // [NLEV, N]    fp32
    float* out = (float*)d_out;                  // [B, N] fp32

    int tot = NLEV * NN * KK;
    prep_kernel<<<(tot + 255) / 256, 256>>>(sidx, w);

    dim3 tblk(32, 32);
    dim3 tin_grid((NN + 31) / 32, BB / 32);
    tin_kernel<<<tin_grid, tblk>>>(x);

    for (int l = 0; l < NLEV; l++) {
        level_kernel<<<NGRID, NTHR>>>(l & 1, l, bias);
    }

    dim3 tout_grid(BB / 32, (NN + 31) / 32);
    tout_kernel<<<tout_grid, tblk>>>(NLEV & 1, out);
}